// round 4
// baseline (speedup 1.0000x reference)
#include <cuda_runtime.h>
#include <math.h>

#define E 128
#define H 8
#define L 2048
#define HE 1024
#define HEL (HE * L)
#define NITEMS 50000
#define WAMT 5

// Scratch (device globals; no allocation allowed)
__device__ float g_I[E * L];        // I[e][l]
__device__ float g_QKV[3 * HEL];    // Q,K,V each [h*E+e][l]
__device__ float g_B[HEL];          // attention output b[h*E+e][l]

// ---------------------------------------------------------------------------
// Kernel 1: build I = W_rep[:,cq] + Item[:,sq]; write I_q^T slab + user_init row
// ---------------------------------------------------------------------------
__global__ void build_I_kernel(const int* __restrict__ sq,
                               const int* __restrict__ cq,
                               const float* __restrict__ ir,
                               const float* __restrict__ wr,
                               const float* __restrict__ uir,
                               float* __restrict__ out) {
    int idx = blockIdx.x * blockDim.x + threadIdx.x;   // idx = l*128 + e
    if (idx < E) out[idx] = uir[idx];                  // u_state row 0 = user_init
    if (idx >= E * L) return;
    int e = idx & 127;
    int l = idx >> 7;
    float iq = ir[e * NITEMS + sq[l]];
    g_I[e * L + l] = iq + wr[e * WAMT + cq[l]];
    out[E * L + idx] = iq;                             // I_q^T at [262144 + l*128 + e]
}

// ---------------------------------------------------------------------------
// Kernel 2: QKV projection. C(1024x2048) = W(1024x128) @ I(128x2048), z=0,1,2
// 64x64 tiles, vectorized loads.
// ---------------------------------------------------------------------------
__global__ __launch_bounds__(256) void gemm_qkv_kernel(const float* __restrict__ Wq,
                                                       const float* __restrict__ Wk,
                                                       const float* __restrict__ Wv) {
    __shared__ float As[64 * 68];   // As[k][m]
    __shared__ float Bs[64 * 68];   // Bs[k][n]
    const float* W = (blockIdx.z == 0) ? Wq : (blockIdx.z == 1 ? Wk : Wv);
    float* C = g_QKV + (size_t)blockIdx.z * HEL;
    const int bm = blockIdx.y * 64;
    const int bn = blockIdx.x * 64;
    const int t = threadIdx.x, tx = t & 15, ty = t >> 4;

    float acc[4][4];
#pragma unroll
    for (int u = 0; u < 4; u++)
#pragma unroll
        for (int v = 0; v < 4; v++) acc[u][v] = 0.f;

    for (int k0 = 0; k0 < 128; k0 += 64) {
        // A tile: 64m x 64k, float4 along k, scalar scatter into As[k][m]
#pragma unroll
        for (int r = 0; r < 4; ++r) {
            int id = t + r * 256;
            int m = id >> 4, kq = id & 15;
            float4 w4 = *(const float4*)&W[(bm + m) * 128 + k0 + kq * 4];
            As[(kq * 4 + 0) * 68 + m] = w4.x;
            As[(kq * 4 + 1) * 68 + m] = w4.y;
            As[(kq * 4 + 2) * 68 + m] = w4.z;
            As[(kq * 4 + 3) * 68 + m] = w4.w;
        }
        // B tile: 64k x 64n, float4 along n
#pragma unroll
        for (int r = 0; r < 4; ++r) {
            int id = t + r * 256;
            int k = id >> 4, n4 = (id & 15) << 2;
            *(float4*)&Bs[k * 68 + n4] =
                *(const float4*)&g_I[(size_t)(k0 + k) * L + bn + n4];
        }
        __syncthreads();
#pragma unroll 8
        for (int k = 0; k < 64; ++k) {
            float4 a4 = *(const float4*)&As[k * 68 + ty * 4];
            float4 b4 = *(const float4*)&Bs[k * 68 + tx * 4];
            float a[4] = {a4.x, a4.y, a4.z, a4.w};
            float b[4] = {b4.x, b4.y, b4.z, b4.w};
#pragma unroll
            for (int u = 0; u < 4; u++)
#pragma unroll
                for (int v = 0; v < 4; v++) acc[u][v] = fmaf(a[u], b[v], acc[u][v]);
        }
        __syncthreads();
    }
#pragma unroll
    for (int u = 0; u < 4; u++) {
        float4 o4 = {acc[u][0], acc[u][1], acc[u][2], acc[u][3]};
        *(float4*)&C[(size_t)(bm + ty * 4 + u) * L + bn + tx * 4] = o4;
    }
}

// ---------------------------------------------------------------------------
// Kernel 3: flash attention, causal-balanced. Per CTA: one head h, query tiles
// {31-pid, pid} (work = 33 key-tiles, constant across all 128 CTAs).
// score[i,j] = (1/sqrt(E)) * sum_e K[h,e,i] Q[h,e,j], causal i<=j, softmax over i,
// B[h,e,j] = sum_i V[h,e,i] * att[i,j].
// ---------------------------------------------------------------------------
#define ATTN_SMEM_FLOATS (8192 + 8192 + 4096 + 64 * 17 + 64 * 3)
#define ATTN_SMEM_BYTES  (ATTN_SMEM_FLOATS * 4)

__global__ __launch_bounds__(256, 2) void attn_kernel() {
    extern __shared__ float sm[];
    float* Qs    = sm;             // [e][jj]  128x64
    float* KVs   = sm + 8192;      // [e][ii]  128x64 (K then V)
    float* Ss    = sm + 16384;     // [ii][jj] 64x64 (p values)
    float* red   = sm + 20480;     // [64][17] partial reductions
    float* m_s   = sm + 21568;     // running max per query col
    float* l_s   = sm + 21632;     // running sum per query col
    float* fac_s = sm + 21696;     // rescale factor per query col

    const int h   = blockIdx.y;
    const int pid = blockIdx.x;
    const int t  = threadIdx.x;
    const int tx = t & 15;
    const int ty = t >> 4;

    const float* Kg = g_QKV + HEL + (size_t)(h * E) * L;
    const float* Vg = g_QKV + 2 * HEL + (size_t)(h * E) * L;
    const float scale = 0.08838834764831845f;   // 1/sqrt(128)

#pragma unroll 1
    for (int tt = 0; tt < 2; ++tt) {
        const int jb = tt ? pid : (31 - pid);   // big tile first
        __syncthreads();   // protect m_s/l_s reinit vs prior tile's reads

        const float* Qg = g_QKV + (size_t)(h * E) * L + jb * 64;
#pragma unroll
        for (int it = 0; it < 8; ++it) {
            int idx = t + it * 256;
            int e = idx >> 4, c4 = (idx & 15) << 2;
            *(float4*)&Qs[e * 64 + c4] = *(const float4*)&Qg[(size_t)e * L + c4];
        }
        if (t < 64) { m_s[t] = -INFINITY; l_s[t] = 0.0f; }

        float acc[8][4];
#pragma unroll
        for (int u = 0; u < 8; u++)
#pragma unroll
            for (int v = 0; v < 4; v++) acc[u][v] = 0.f;

        for (int ib = 0; ib <= jb; ++ib) {
            __syncthreads();   // S1: prev PV reads done; Q/init visible on first iter
            const float* Kt = Kg + ib * 64;
            const float* Vt = Vg + ib * 64;
#pragma unroll
            for (int it = 0; it < 8; ++it) {
                int idx = t + it * 256;
                int e = idx >> 4, c4 = (idx & 15) << 2;
                *(float4*)&KVs[e * 64 + c4] = *(const float4*)&Kt[(size_t)e * L + c4];
            }
            __syncthreads();   // S2: K tile ready

            // Phase A: scores s[ii=ty*4+u][jj=tx*4+v]
            float s[4][4];
#pragma unroll
            for (int u = 0; u < 4; u++)
#pragma unroll
                for (int v = 0; v < 4; v++) s[u][v] = 0.f;
#pragma unroll 4
            for (int e = 0; e < 128; ++e) {
                float4 kk = *(const float4*)&KVs[e * 64 + ty * 4];
                float4 qq = *(const float4*)&Qs[e * 64 + tx * 4];
                float ka[4] = {kk.x, kk.y, kk.z, kk.w};
                float qa[4] = {qq.x, qq.y, qq.z, qq.w};
#pragma unroll
                for (int u = 0; u < 4; u++)
#pragma unroll
                    for (int v = 0; v < 4; v++) s[u][v] = fmaf(ka[u], qa[v], s[u][v]);
            }
            if (ib == jb) {
#pragma unroll
                for (int u = 0; u < 4; u++)
#pragma unroll
                    for (int v = 0; v < 4; v++)
                        s[u][v] = (ty * 4 + u > tx * 4 + v) ? -1e30f : s[u][v] * scale;
            } else {
#pragma unroll
                for (int u = 0; u < 4; u++)
#pragma unroll
                    for (int v = 0; v < 4; v++) s[u][v] *= scale;
            }

            // per-column (query) partial max -> red[jj][ty]
#pragma unroll
            for (int v = 0; v < 4; v++) {
                float mx = fmaxf(fmaxf(s[0][v], s[1][v]), fmaxf(s[2][v], s[3][v]));
                red[(tx * 4 + v) * 17 + ty] = mx;
            }
            __syncthreads();   // S3: red ready, K reads finished

            // load V tile (overwrites K) while 64 threads finish the max reduction
#pragma unroll
            for (int it = 0; it < 8; ++it) {
                int idx = t + it * 256;
                int e = idx >> 4, c4 = (idx & 15) << 2;
                *(float4*)&KVs[e * 64 + c4] = *(const float4*)&Vt[(size_t)e * L + c4];
            }
            if (t < 64) {
                float mx = red[t * 17];
#pragma unroll
                for (int y = 1; y < 16; y++) mx = fmaxf(mx, red[t * 17 + y]);
                float mo = m_s[t];
                float mn = fmaxf(mo, mx);
                m_s[t] = mn;
                fac_s[t] = __expf(mo - mn);
            }
            __syncthreads();   // S4: V ready, m/fac ready

            // Phase P: rescale acc, p = exp(s - m), store to Ss, partial sums
            float mv[4], fv[4], psum[4];
#pragma unroll
            for (int v = 0; v < 4; v++) {
                mv[v] = m_s[tx * 4 + v];
                fv[v] = fac_s[tx * 4 + v];
                psum[v] = 0.f;
            }
#pragma unroll
            for (int u = 0; u < 8; u++)
#pragma unroll
                for (int v = 0; v < 4; v++) acc[u][v] *= fv[v];
#pragma unroll
            for (int u = 0; u < 4; u++) {
                float p0 = __expf(s[u][0] - mv[0]); psum[0] += p0;
                float p1 = __expf(s[u][1] - mv[1]); psum[1] += p1;
                float p2 = __expf(s[u][2] - mv[2]); psum[2] += p2;
                float p3 = __expf(s[u][3] - mv[3]); psum[3] += p3;
                float4 pr = {p0, p1, p2, p3};
                *(float4*)&Ss[(ty * 4 + u) * 64 + tx * 4] = pr;
            }
#pragma unroll
            for (int v = 0; v < 4; v++) red[(tx * 4 + v) * 17 + ty] = psum[v];
            __syncthreads();   // S5: p + partial sums ready

            if (t < 64) {
                float sum = 0.f;
#pragma unroll
                for (int y = 0; y < 16; y++) sum += red[t * 17 + y];
                l_s[t] = l_s[t] * fac_s[t] + sum;
            }

            // Phase B (vectorized): acc[e=ty*8+u][jj=tx*4+v] += sum_ii V[e][ii]*p[ii][jj]
#pragma unroll 2
            for (int ii0 = 0; ii0 < 64; ii0 += 4) {
                float4 p0 = *(const float4*)&Ss[(ii0 + 0) * 64 + tx * 4];
                float4 p1 = *(const float4*)&Ss[(ii0 + 1) * 64 + tx * 4];
                float4 p2 = *(const float4*)&Ss[(ii0 + 2) * 64 + tx * 4];
                float4 p3 = *(const float4*)&Ss[(ii0 + 3) * 64 + tx * 4];
#pragma unroll
                for (int u = 0; u < 8; u++) {
                    float4 v4 = *(const float4*)&KVs[(ty * 8 + u) * 64 + ii0];
                    acc[u][0] = fmaf(v4.x, p0.x, acc[u][0]);
                    acc[u][1] = fmaf(v4.x, p0.y, acc[u][1]);
                    acc[u][2] = fmaf(v4.x, p0.z, acc[u][2]);
                    acc[u][3] = fmaf(v4.x, p0.w, acc[u][3]);
                    acc[u][0] = fmaf(v4.y, p1.x, acc[u][0]);
                    acc[u][1] = fmaf(v4.y, p1.y, acc[u][1]);
                    acc[u][2] = fmaf(v4.y, p1.z, acc[u][2]);
                    acc[u][3] = fmaf(v4.y, p1.w, acc[u][3]);
                    acc[u][0] = fmaf(v4.z, p2.x, acc[u][0]);
                    acc[u][1] = fmaf(v4.z, p2.y, acc[u][1]);
                    acc[u][2] = fmaf(v4.z, p2.z, acc[u][2]);
                    acc[u][3] = fmaf(v4.z, p2.w, acc[u][3]);
                    acc[u][0] = fmaf(v4.w, p3.x, acc[u][0]);
                    acc[u][1] = fmaf(v4.w, p3.y, acc[u][1]);
                    acc[u][2] = fmaf(v4.w, p3.z, acc[u][2]);
                    acc[u][3] = fmaf(v4.w, p3.w, acc[u][3]);
                }
            }
        }
        __syncthreads();   // l_s final visible to everyone

        float linv[4];
#pragma unroll
        for (int v = 0; v < 4; v++) linv[v] = 1.0f / l_s[tx * 4 + v];
        float* outp = g_B + (size_t)(h * E + ty * 8) * L + jb * 64 + tx * 4;
#pragma unroll
        for (int u = 0; u < 8; u++) {
            float4 o4 = {acc[u][0] * linv[0], acc[u][1] * linv[1],
                         acc[u][2] * linv[2], acc[u][3] * linv[3]};
            *(float4*)&outp[(size_t)u * L] = o4;
        }
    }
}

// ---------------------------------------------------------------------------
// Kernel 4: o = Head_agg(128x1024) @ B(1024x2048), scattered into output layout
// 64x32 tiles -> 128 CTAs, float4 loads. out[128+j*128+e] (j<2047), out[524288+e]
// ---------------------------------------------------------------------------
__global__ __launch_bounds__(256) void gemm_out_kernel(const float* __restrict__ A,
                                                       float* __restrict__ out) {
    __shared__ float As[64 * 66];   // As[k][m], 64k x 64m
    __shared__ float Bs[64 * 36];   // Bs[k][n], 64k x 32n
    const int bm = blockIdx.y * 64;
    const int bn = blockIdx.x * 32;
    const int t = threadIdx.x, tx = t & 7, ty = t >> 3;   // ty: 0..31

    float acc[2][4];
#pragma unroll
    for (int u = 0; u < 2; u++)
#pragma unroll
        for (int v = 0; v < 4; v++) acc[u][v] = 0.f;

    for (int k0 = 0; k0 < 1024; k0 += 64) {
        // A tile: 64m x 64k, float4 along k
#pragma unroll
        for (int r = 0; r < 4; ++r) {
            int id = t + r * 256;
            int m = id >> 4, kq = id & 15;
            float4 a4 = *(const float4*)&A[(bm + m) * 1024 + k0 + kq * 4];
            As[(kq * 4 + 0) * 66 + m] = a4.x;
            As[(kq * 4 + 1) * 66 + m] = a4.y;
            As[(kq * 4 + 2) * 66 + m] = a4.z;
            As[(kq * 4 + 3) * 66 + m] = a4.w;
        }
        // B tile: 64k x 32n, float4 along n
#pragma unroll
        for (int r = 0; r < 2; ++r) {
            int id = t + r * 256;
            int k = id >> 3, n4 = (id & 7) << 2;
            *(float4*)&Bs[k * 36 + n4] =
                *(const float4*)&g_B[(size_t)(k0 + k) * L + bn + n4];
        }
        __syncthreads();
#pragma unroll 8
        for (int k = 0; k < 64; ++k) {
            float2 a2 = *(const float2*)&As[k * 66 + ty * 2];
            float4 b4 = *(const float4*)&Bs[k * 36 + tx * 4];
            acc[0][0] = fmaf(a2.x, b4.x, acc[0][0]);
            acc[0][1] = fmaf(a2.x, b4.y, acc[0][1]);
            acc[0][2] = fmaf(a2.x, b4.z, acc[0][2]);
            acc[0][3] = fmaf(a2.x, b4.w, acc[0][3]);
            acc[1][0] = fmaf(a2.y, b4.x, acc[1][0]);
            acc[1][1] = fmaf(a2.y, b4.y, acc[1][1]);
            acc[1][2] = fmaf(a2.y, b4.z, acc[1][2]);
            acc[1][3] = fmaf(a2.y, b4.w, acc[1][3]);
        }
        __syncthreads();
    }
#pragma unroll
    for (int u = 0; u < 2; u++) {
#pragma unroll
        for (int v = 0; v < 4; v++) {
            int e = bm + ty * 2 + u;
            int j = bn + tx * 4 + v;
            int dst = (j < L - 1) ? (E + j * E + e) : (2 * E * L + e);
            out[dst] = acc[u][v];
        }
    }
}

// ---------------------------------------------------------------------------
extern "C" void kernel_launch(void* const* d_in, const int* in_sizes, int n_in,
                              void* d_out, int out_size) {
    const int*   sq   = (const int*)d_in[0];
    const int*   cq   = (const int*)d_in[1];
    const float* ir   = (const float*)d_in[2];
    const float* uir  = (const float*)d_in[3];
    const float* wr   = (const float*)d_in[4];
    const float* Wq   = (const float*)d_in[5];
    const float* Wk   = (const float*)d_in[6];
    const float* Wv   = (const float*)d_in[7];
    const float* Hagg = (const float*)d_in[8];
    float* out = (float*)d_out;

    cudaFuncSetAttribute(attn_kernel, cudaFuncAttributeMaxDynamicSharedMemorySize,
                         ATTN_SMEM_BYTES);

    build_I_kernel<<<(E * L) / 256, 256>>>(sq, cq, ir, wr, uir, out);
    gemm_qkv_kernel<<<dim3(32, 16, 3), 256>>>(Wq, Wk, Wv);
    attn_kernel<<<dim3(16, H), 256, ATTN_SMEM_BYTES>>>();
    gemm_out_kernel<<<dim3(64, 2), 256>>>(Hagg, out);
}

// round 6
// speedup vs baseline: 1.4839x; 1.4839x over previous
#include <cuda_runtime.h>
#include <cuda_bf16.h>
#include <math.h>
#include <stdint.h>

#define E 128
#define H 8
#define L 2048
#define HE 1024
#define HEL (HE * L)
#define NITEMS 50000
#define WAMT 5
#define SCALE_F 0.08838834764831845f

__device__ float g_I[E * L];
__device__ float g_QKV[3 * HEL];
__device__ float g_B[HEL];

__device__ __forceinline__ uint32_t smem_u32(const void* p) {
    return (uint32_t)__cvta_generic_to_shared(p);
}
__device__ __forceinline__ void ldsm4(uint32_t* r, uint32_t a) {
    asm volatile("ldmatrix.sync.aligned.m8n8.x4.shared.b16 {%0,%1,%2,%3}, [%4];"
                 : "=r"(r[0]), "=r"(r[1]), "=r"(r[2]), "=r"(r[3]) : "r"(a));
}
__device__ __forceinline__ void ldsm4t(uint32_t* r, uint32_t a) {
    asm volatile("ldmatrix.sync.aligned.m8n8.x4.trans.shared.b16 {%0,%1,%2,%3}, [%4];"
                 : "=r"(r[0]), "=r"(r[1]), "=r"(r[2]), "=r"(r[3]) : "r"(a));
}
__device__ __forceinline__ void mma_bf16(float* c, const uint32_t* a, const uint32_t* b) {
    asm volatile("mma.sync.aligned.m16n8k16.row.col.f32.bf16.bf16.f32 "
                 "{%0,%1,%2,%3}, {%4,%5,%6,%7}, {%8,%9}, {%0,%1,%2,%3};"
                 : "+f"(c[0]), "+f"(c[1]), "+f"(c[2]), "+f"(c[3])
                 : "r"(a[0]), "r"(a[1]), "r"(a[2]), "r"(a[3]), "r"(b[0]), "r"(b[1]));
}
__device__ __forceinline__ void split2(float a, float b, __nv_bfloat162& h, __nv_bfloat162& l) {
    h = __floats2bfloat162_rn(a, b);
    float2 r = __bfloat1622float2(h);
    l = __floats2bfloat162_rn(a - r.x, b - r.y);
}

// ---------------------------------------------------------------------------
__global__ void build_I_kernel(const int* __restrict__ sq, const int* __restrict__ cq,
                               const float* __restrict__ ir, const float* __restrict__ wr,
                               const float* __restrict__ uir, float* __restrict__ out) {
    int idx = blockIdx.x * blockDim.x + threadIdx.x;
    if (idx < E) out[idx] = uir[idx];
    if (idx >= E * L) return;
    int e = idx & 127, l = idx >> 7;
    float iq = ir[e * NITEMS + sq[l]];
    g_I[e * L + l] = iq + wr[e * WAMT + cq[l]];
    out[E * L + idx] = iq;
}

// ---------------------------------------------------------------------------
__global__ __launch_bounds__(256) void gemm_qkv_kernel(const float* __restrict__ Wq,
                                                       const float* __restrict__ Wk,
                                                       const float* __restrict__ Wv) {
    __shared__ float As[64 * 68], Bs[64 * 68];
    const float* W = (blockIdx.z == 0) ? Wq : (blockIdx.z == 1 ? Wk : Wv);
    float* C = g_QKV + (size_t)blockIdx.z * HEL;
    const int bm = blockIdx.y * 64, bn = blockIdx.x * 64;
    const int t = threadIdx.x, tx = t & 15, ty = t >> 4;
    float acc[4][4];
#pragma unroll
    for (int u = 0; u < 4; u++)
#pragma unroll
        for (int v = 0; v < 4; v++) acc[u][v] = 0.f;
    for (int k0 = 0; k0 < 128; k0 += 64) {
#pragma unroll
        for (int r = 0; r < 4; ++r) {
            int id = t + r * 256, m = id >> 4, kq = id & 15;
            float4 w4 = *(const float4*)&W[(bm + m) * 128 + k0 + kq * 4];
            As[(kq * 4 + 0) * 68 + m] = w4.x; As[(kq * 4 + 1) * 68 + m] = w4.y;
            As[(kq * 4 + 2) * 68 + m] = w4.z; As[(kq * 4 + 3) * 68 + m] = w4.w;
        }
#pragma unroll
        for (int r = 0; r < 4; ++r) {
            int id = t + r * 256, k = id >> 4, n4 = (id & 15) << 2;
            *(float4*)&Bs[k * 68 + n4] = *(const float4*)&g_I[(size_t)(k0 + k) * L + bn + n4];
        }
        __syncthreads();
#pragma unroll 8
        for (int k = 0; k < 64; ++k) {
            float4 a4 = *(const float4*)&As[k * 68 + ty * 4];
            float4 b4 = *(const float4*)&Bs[k * 68 + tx * 4];
            float a[4] = {a4.x, a4.y, a4.z, a4.w}, b[4] = {b4.x, b4.y, b4.z, b4.w};
#pragma unroll
            for (int u = 0; u < 4; u++)
#pragma unroll
                for (int v = 0; v < 4; v++) acc[u][v] = fmaf(a[u], b[v], acc[u][v]);
        }
        __syncthreads();
    }
#pragma unroll
    for (int u = 0; u < 4; u++) {
        float4 o4 = {acc[u][0], acc[u][1], acc[u][2], acc[u][3]};
        *(float4*)&C[(size_t)(bm + ty * 4 + u) * L + bn + tx * 4] = o4;
    }
}

// ---------------------------------------------------------------------------
// mma.sync flash attention. Per CTA: head h, q-tiles {31-px, px} of 64.
// KV steps of 64 keys. S: warp (wi,wj) -> 16i x 32j. PV: warp w -> 16e x 64j.
// smem: Q[j][e] hi/lo (stride 136), K[i][e] hi/lo (136), V[e][i] hi/lo (72),
//       P[i][j] hi/lo (72), all bf16.
// ---------------------------------------------------------------------------
#define SQK 136
#define SVP 72
#define S_QH 0
#define S_QL 17408
#define S_KH 34816
#define S_KL 52224
#define S_VH 69632
#define S_VL 88064
#define S_PH 106496
#define S_PL 115712
#define S_LS 124928
#define S_RED 125184
#define ATTN_SMEM 126208

__global__ __launch_bounds__(256, 1) void attn_kernel() {
    extern __shared__ __align__(128) char smc[];
    const uint32_t sb = smem_u32(smc);
    const int t = threadIdx.x, w = t >> 5, ln = t & 31;
    const int h = blockIdx.y, px = blockIdx.x;
    float* l_s = (float*)(smc + S_LS);
    float* red = (float*)(smc + S_RED);

    const float* Qg = g_QKV + (size_t)(h * E) * L;
    const float* Kg = Qg + HEL;
    const float* Vg = Qg + 2 * HEL;

    const int wi = w & 3, wj = w >> 2;
    const int iw = wi * 16, jw = wj * 32;
    const int mA = ln >> 3;
    const int g8 = ln & 7;
    // S-phase ldmatrix lane rows/cols
    const int sArow = iw + g8 + (mA & 1) * 8;     // K row (local i)
    const int sAcol = (mA >> 1) * 8;              // + e0
    const int sBrow = g8 + (mA >> 1) * 8;         // + j16 (Q row)
    const int sBcol = (mA & 1) * 8;               // + e0
    // PV-phase
    const int ew = w * 16;
    const int pArow = ew + g8 + (mA & 1) * 8;     // V row (e)
    const int pAcol = (mA >> 1) * 8;              // + i0
    const int pBrow = g8 + (mA & 1) * 8;          // + i0 (P row)
    const int pBcol = (mA >> 1) * 8;              // + j16

#pragma unroll 1
    for (int ts = 0; ts < 2; ++ts) {
        const int jt = ts ? px : (31 - px);
        const int qb = jt << 6;
        __syncthreads();   // prior epilogue reads done before overwriting Q/l_s

        // Q load + scale + split -> [j][e] hi/lo
#pragma unroll
        for (int r = 0; r < 4; ++r) {
            int id = t + r * 256, ep = id >> 4, j4 = (id & 15) << 2, e = ep * 2;
            float4 f0 = *(const float4*)&Qg[(size_t)e * L + qb + j4];
            float4 f1 = *(const float4*)&Qg[(size_t)(e + 1) * L + qb + j4];
            float a0[4] = {f0.x, f0.y, f0.z, f0.w}, a1[4] = {f1.x, f1.y, f1.z, f1.w};
#pragma unroll
            for (int c = 0; c < 4; ++c) {
                __nv_bfloat162 hh, ll;
                split2(a0[c] * SCALE_F, a1[c] * SCALE_F, hh, ll);
                int off = ((j4 + c) * SQK + e) * 2;
                *(__nv_bfloat162*)(smc + S_QH + off) = hh;
                *(__nv_bfloat162*)(smc + S_QL + off) = ll;
            }
        }
        if (t < 64) l_s[t] = 0.f;

        float bacc[8][4];
#pragma unroll
        for (int u = 0; u < 8; u++)
#pragma unroll
            for (int v = 0; v < 4; v++) bacc[u][v] = 0.f;

#pragma unroll 1
        for (int ib = 0; ib <= jt; ++ib) {
            __syncthreads();   // prev PV reads done; Q visible on first iter
            // K tile -> [i][e] hi/lo (transpose)
#pragma unroll
            for (int r = 0; r < 4; ++r) {
                int id = t + r * 256, ep = id >> 4, i4 = (id & 15) << 2, e = ep * 2;
                float4 f0 = *(const float4*)&Kg[(size_t)e * L + ib * 64 + i4];
                float4 f1 = *(const float4*)&Kg[(size_t)(e + 1) * L + ib * 64 + i4];
                float a0[4] = {f0.x, f0.y, f0.z, f0.w}, a1[4] = {f1.x, f1.y, f1.z, f1.w};
#pragma unroll
                for (int c = 0; c < 4; ++c) {
                    __nv_bfloat162 hh, ll;
                    split2(a0[c], a1[c], hh, ll);
                    int off = ((i4 + c) * SQK + e) * 2;
                    *(__nv_bfloat162*)(smc + S_KH + off) = hh;
                    *(__nv_bfloat162*)(smc + S_KL + off) = ll;
                }
            }
            // V tile -> [e][i] hi/lo (direct)
#pragma unroll
            for (int r = 0; r < 8; ++r) {
                int id = t + r * 256, e = id >> 4, i4 = (id & 15) << 2;
                float4 f = *(const float4*)&Vg[(size_t)e * L + ib * 64 + i4];
                __nv_bfloat162 ha, la, hb, lb;
                split2(f.x, f.y, ha, la);
                split2(f.z, f.w, hb, lb);
                int o1 = (e * SVP + i4) * 2;
                *(__nv_bfloat162*)(smc + S_VH + o1) = ha;
                *(__nv_bfloat162*)(smc + S_VH + o1 + 4) = hb;
                *(__nv_bfloat162*)(smc + S_VL + o1) = la;
                *(__nv_bfloat162*)(smc + S_VL + o1 + 4) = lb;
            }
            __syncthreads();   // K/V ready

            // ---- S = K^T Q (16i x 32j per warp), 3-term compensated ----
            float sacc[4][4];
#pragma unroll
            for (int u = 0; u < 4; u++)
#pragma unroll
                for (int v = 0; v < 4; v++) sacc[u][v] = 0.f;
#pragma unroll
            for (int ks = 0; ks < 8; ++ks) {
                int e0 = ks * 16;
                uint32_t ah[4], al[4];
                ldsm4(ah, sb + S_KH + (uint32_t)((sArow * SQK + e0 + sAcol) * 2));
                ldsm4(al, sb + S_KL + (uint32_t)((sArow * SQK + e0 + sAcol) * 2));
#pragma unroll
                for (int np = 0; np < 2; ++np) {
                    int j16 = jw + np * 16;
                    uint32_t bh[4], bl[4];
                    uint32_t boff = (uint32_t)(((j16 + sBrow) * SQK + e0 + sBcol) * 2);
                    ldsm4(bh, sb + S_QH + boff);
                    ldsm4(bl, sb + S_QL + boff);
                    mma_bf16(sacc[np * 2], ah, bh);
                    mma_bf16(sacc[np * 2], ah, bl);
                    mma_bf16(sacc[np * 2], al, bh);
                    mma_bf16(sacc[np * 2 + 1], ah, bh + 2);
                    mma_bf16(sacc[np * 2 + 1], ah, bl + 2);
                    mma_bf16(sacc[np * 2 + 1], al, bh + 2);
                }
            }

            // ---- exp + causal mask + store P hi/lo + column sums ----
            const int rl0 = iw + (ln >> 2);
            const int i0g = ib * 64 + rl0;
#pragma unroll
            for (int nt = 0; nt < 4; ++nt) {
                int jc = jw + nt * 8 + (ln & 3) * 2;
                int jg = qb + jc;
                float p0 = (i0g <= jg)     ? __expf(sacc[nt][0]) : 0.f;
                float p1 = (i0g <= jg + 1) ? __expf(sacc[nt][1]) : 0.f;
                float p2 = (i0g + 8 <= jg)     ? __expf(sacc[nt][2]) : 0.f;
                float p3 = (i0g + 8 <= jg + 1) ? __expf(sacc[nt][3]) : 0.f;
                __nv_bfloat162 h01, l01, h23, l23;
                split2(p0, p1, h01, l01);
                split2(p2, p3, h23, l23);
                int o0 = (rl0 * SVP + jc) * 2;
                int o1 = ((rl0 + 8) * SVP + jc) * 2;
                *(__nv_bfloat162*)(smc + S_PH + o0) = h01;
                *(__nv_bfloat162*)(smc + S_PH + o1) = h23;
                *(__nv_bfloat162*)(smc + S_PL + o0) = l01;
                *(__nv_bfloat162*)(smc + S_PL + o1) = l23;
                float cs0 = p0 + p2, cs1 = p1 + p3;
#pragma unroll
                for (int off = 4; off < 32; off <<= 1) {
                    cs0 += __shfl_xor_sync(0xffffffffu, cs0, off);
                    cs1 += __shfl_xor_sync(0xffffffffu, cs1, off);
                }
                if (ln < 4) { red[wi * 64 + jc] = cs0; red[wi * 64 + jc + 1] = cs1; }
            }
            __syncthreads();   // P + red ready
            if (t < 64) l_s[t] += red[t] + red[64 + t] + red[128 + t] + red[192 + t];

            // ---- PV: bacc(16e x 64j per warp) += V @ P, 3-term ----
#pragma unroll
            for (int ks = 0; ks < 4; ++ks) {
                int i0 = ks * 16;
                uint32_t ah[4], al[4];
                uint32_t aoff = (uint32_t)((pArow * SVP + i0 + pAcol) * 2);
                ldsm4(ah, sb + S_VH + aoff);
                ldsm4(al, sb + S_VL + aoff);
#pragma unroll
                for (int np = 0; np < 4; ++np) {
                    int j16 = np * 16;
                    uint32_t bh[4], bl[4];
                    uint32_t boff = (uint32_t)(((i0 + pBrow) * SVP + j16 + pBcol) * 2);
                    ldsm4t(bh, sb + S_PH + boff);
                    ldsm4t(bl, sb + S_PL + boff);
                    mma_bf16(bacc[np * 2], ah, bh);
                    mma_bf16(bacc[np * 2], ah, bl);
                    mma_bf16(bacc[np * 2], al, bh);
                    mma_bf16(bacc[np * 2 + 1], ah, bh + 2);
                    mma_bf16(bacc[np * 2 + 1], ah, bl + 2);
                    mma_bf16(bacc[np * 2 + 1], al, bh + 2);
                }
            }
        }
        __syncthreads();   // l_s final

        // epilogue: normalize + store to g_B[h*E+e][l]
        const int r0 = ew + (ln >> 2);
#pragma unroll
        for (int nt = 0; nt < 8; ++nt) {
            int jc = nt * 8 + (ln & 3) * 2;
            float li0 = 1.0f / l_s[jc], li1 = 1.0f / l_s[jc + 1];
            float2 o0 = {bacc[nt][0] * li0, bacc[nt][1] * li1};
            float2 o1 = {bacc[nt][2] * li0, bacc[nt][3] * li1};
            *(float2*)&g_B[(size_t)(h * E + r0) * L + qb + jc] = o0;
            *(float2*)&g_B[(size_t)(h * E + r0 + 8) * L + qb + jc] = o1;
        }
    }
}

// ---------------------------------------------------------------------------
__global__ __launch_bounds__(256) void gemm_out_kernel(const float* __restrict__ A,
                                                       float* __restrict__ out) {
    __shared__ float As[64 * 66], Bs[64 * 36];
    const int bm = blockIdx.y * 64, bn = blockIdx.x * 32;
    const int t = threadIdx.x, tx = t & 7, ty = t >> 3;
    float acc[2][4];
#pragma unroll
    for (int u = 0; u < 2; u++)
#pragma unroll
        for (int v = 0; v < 4; v++) acc[u][v] = 0.f;
    for (int k0 = 0; k0 < 1024; k0 += 64) {
#pragma unroll
        for (int r = 0; r < 4; ++r) {
            int id = t + r * 256, m = id >> 4, kq = id & 15;
            float4 a4 = *(const float4*)&A[(bm + m) * 1024 + k0 + kq * 4];
            As[(kq * 4 + 0) * 66 + m] = a4.x; As[(kq * 4 + 1) * 66 + m] = a4.y;
            As[(kq * 4 + 2) * 66 + m] = a4.z; As[(kq * 4 + 3) * 66 + m] = a4.w;
        }
#pragma unroll
        for (int r = 0; r < 2; ++r) {
            int id = t + r * 256, k = id >> 3, n4 = (id & 7) << 2;
            *(float4*)&Bs[k * 36 + n4] = *(const float4*)&g_B[(size_t)(k0 + k) * L + bn + n4];
        }
        __syncthreads();
#pragma unroll 8
        for (int k = 0; k < 64; ++k) {
            float2 a2 = *(const float2*)&As[k * 66 + ty * 2];
            float4 b4 = *(const float4*)&Bs[k * 36 + tx * 4];
            acc[0][0] = fmaf(a2.x, b4.x, acc[0][0]); acc[0][1] = fmaf(a2.x, b4.y, acc[0][1]);
            acc[0][2] = fmaf(a2.x, b4.z, acc[0][2]); acc[0][3] = fmaf(a2.x, b4.w, acc[0][3]);
            acc[1][0] = fmaf(a2.y, b4.x, acc[1][0]); acc[1][1] = fmaf(a2.y, b4.y, acc[1][1]);
            acc[1][2] = fmaf(a2.y, b4.z, acc[1][2]); acc[1][3] = fmaf(a2.y, b4.w, acc[1][3]);
        }
        __syncthreads();
    }
#pragma unroll
    for (int u = 0; u < 2; u++)
#pragma unroll
        for (int v = 0; v < 4; v++) {
            int e = bm + ty * 2 + u, j = bn + tx * 4 + v;
            out[(j < L - 1) ? (E + j * E + e) : (2 * E * L + e)] = acc[u][v];
        }
}

// ---------------------------------------------------------------------------
extern "C" void kernel_launch(void* const* d_in, const int* in_sizes, int n_in,
                              void* d_out, int out_size) {
    const int* sq = (const int*)d_in[0];
    const int* cq = (const int*)d_in[1];
    const float* ir = (const float*)d_in[2];
    const float* uir = (const float*)d_in[3];
    const float* wr = (const float*)d_in[4];
    const float* Wq = (const float*)d_in[5];
    const float* Wk = (const float*)d_in[6];
    const float* Wv = (const float*)d_in[7];
    const float* Hagg = (const float*)d_in[8];
    float* out = (float*)d_out;
    cudaFuncSetAttribute(attn_kernel, cudaFuncAttributeMaxDynamicSharedMemorySize, ATTN_SMEM);
    build_I_kernel<<<(E * L) / 256, 256>>>(sq, cq, ir, wr, uir, out);
    gemm_qkv_kernel<<<dim3(32, 16, 3), 256>>>(Wq, Wk, Wv);
    attn_kernel<<<dim3(16, H), 256, ATTN_SMEM>>>();
    gemm_out_kernel<<<dim3(64, 2), 256>>>(Hagg, out);
}

// round 7
// speedup vs baseline: 1.6998x; 1.1455x over previous
#include <cuda_runtime.h>
#include <cuda_bf16.h>
#include <math.h>
#include <stdint.h>

#define E 128
#define H 8
#define L 2048
#define HE 1024
#define HEL (HE * L)
#define NITEMS 50000
#define WAMT 5
#define SCALE_F 0.08838834764831845f

__device__ float g_I[E * L];
// Packed bf16 hi/lo operands
__device__ __nv_bfloat16 g_Qh[H * L * E], g_Ql[H * L * E];   // [h][l][e], pre-scaled
__device__ __nv_bfloat16 g_Kh[H * L * E], g_Kl[H * L * E];   // [h][l][e]
__device__ __nv_bfloat16 g_Vh[H * E * L], g_Vl[H * E * L];   // [h][e][l]
__device__ __nv_bfloat16 g_bh[L * HE], g_bl[L * HE];         // [l][he]
__device__ __nv_bfloat16 g_Ah[E * HE], g_Al[E * HE];         // [e_out][k]

__device__ __forceinline__ uint32_t smem_u32(const void* p) {
    return (uint32_t)__cvta_generic_to_shared(p);
}
__device__ __forceinline__ void ldsm4(uint32_t* r, uint32_t a) {
    asm volatile("ldmatrix.sync.aligned.m8n8.x4.shared.b16 {%0,%1,%2,%3}, [%4];"
                 : "=r"(r[0]), "=r"(r[1]), "=r"(r[2]), "=r"(r[3]) : "r"(a));
}
__device__ __forceinline__ void ldsm4t(uint32_t* r, uint32_t a) {
    asm volatile("ldmatrix.sync.aligned.m8n8.x4.trans.shared.b16 {%0,%1,%2,%3}, [%4];"
                 : "=r"(r[0]), "=r"(r[1]), "=r"(r[2]), "=r"(r[3]) : "r"(a));
}
__device__ __forceinline__ void mma_bf16(float* c, const uint32_t* a, const uint32_t* b) {
    asm volatile("mma.sync.aligned.m16n8k16.row.col.f32.bf16.bf16.f32 "
                 "{%0,%1,%2,%3}, {%4,%5,%6,%7}, {%8,%9}, {%0,%1,%2,%3};"
                 : "+f"(c[0]), "+f"(c[1]), "+f"(c[2]), "+f"(c[3])
                 : "r"(a[0]), "r"(a[1]), "r"(a[2]), "r"(a[3]), "r"(b[0]), "r"(b[1]));
}
__device__ __forceinline__ void split2(float a, float b, __nv_bfloat162& h, __nv_bfloat162& l) {
    h = __floats2bfloat162_rn(a, b);
    float2 r = __bfloat1622float2(h);
    l = __floats2bfloat162_rn(a - r.x, b - r.y);
}

// ---------------------------------------------------------------------------
__global__ void build_I_kernel(const int* __restrict__ sq, const int* __restrict__ cq,
                               const float* __restrict__ ir, const float* __restrict__ wr,
                               const float* __restrict__ uir, float* __restrict__ out) {
    int idx = blockIdx.x * blockDim.x + threadIdx.x;
    if (idx < E) out[idx] = uir[idx];
    if (idx >= E * L) return;
    int e = idx & 127, l = idx >> 7;
    float iq = ir[e * NITEMS + sq[l]];
    g_I[e * L + l] = iq + wr[e * WAMT + cq[l]];
    out[E * L + idx] = iq;
}

// Split Head_agg into bf16 hi/lo [e][k]
__global__ void prep_A_kernel(const float* __restrict__ A) {
    int idx = blockIdx.x * blockDim.x + threadIdx.x;   // 0..65535, 2 elems each
    int i2 = idx * 2;
    float2 f = *(const float2*)&A[i2];
    __nv_bfloat162 hh, ll;
    split2(f.x, f.y, hh, ll);
    *(__nv_bfloat162*)&g_Ah[i2] = hh;
    *(__nv_bfloat162*)&g_Al[i2] = ll;
}

// ---------------------------------------------------------------------------
// QKV projection with bf16 hi/lo pack epilogue (no fp32 QKV output).
// ---------------------------------------------------------------------------
__global__ __launch_bounds__(256) void gemm_qkv_kernel(const float* __restrict__ Wq,
                                                       const float* __restrict__ Wk,
                                                       const float* __restrict__ Wv) {
    __shared__ float As[64 * 68], Bs[64 * 68];
    const float* W = (blockIdx.z == 0) ? Wq : (blockIdx.z == 1 ? Wk : Wv);
    const int bm = blockIdx.y * 64, bn = blockIdx.x * 64;
    const int t = threadIdx.x, tx = t & 15, ty = t >> 4;
    float acc[4][4];
#pragma unroll
    for (int u = 0; u < 4; u++)
#pragma unroll
        for (int v = 0; v < 4; v++) acc[u][v] = 0.f;
    for (int k0 = 0; k0 < 128; k0 += 64) {
#pragma unroll
        for (int r = 0; r < 4; ++r) {
            int id = t + r * 256, m = id >> 4, kq = id & 15;
            float4 w4 = *(const float4*)&W[(bm + m) * 128 + k0 + kq * 4];
            As[(kq * 4 + 0) * 68 + m] = w4.x; As[(kq * 4 + 1) * 68 + m] = w4.y;
            As[(kq * 4 + 2) * 68 + m] = w4.z; As[(kq * 4 + 3) * 68 + m] = w4.w;
        }
#pragma unroll
        for (int r = 0; r < 4; ++r) {
            int id = t + r * 256, k = id >> 4, n4 = (id & 15) << 2;
            *(float4*)&Bs[k * 68 + n4] = *(const float4*)&g_I[(size_t)(k0 + k) * L + bn + n4];
        }
        __syncthreads();
#pragma unroll 8
        for (int k = 0; k < 64; ++k) {
            float4 a4 = *(const float4*)&As[k * 68 + ty * 4];
            float4 b4 = *(const float4*)&Bs[k * 68 + tx * 4];
            float a[4] = {a4.x, a4.y, a4.z, a4.w}, b[4] = {b4.x, b4.y, b4.z, b4.w};
#pragma unroll
            for (int u = 0; u < 4; u++)
#pragma unroll
                for (int v = 0; v < 4; v++) acc[u][v] = fmaf(a[u], b[v], acc[u][v]);
        }
        __syncthreads();
    }
    const int m0 = bm + ty * 4;            // he dim
    const int n0 = bn + tx * 4;            // l dim
    const int h = m0 >> 7, e0 = m0 & 127;
    if (blockIdx.z < 2) {                  // Q or K -> [h][l][e]
        __nv_bfloat16* Dh = blockIdx.z ? g_Kh : g_Qh;
        __nv_bfloat16* Dl = blockIdx.z ? g_Kl : g_Ql;
        const float s = blockIdx.z ? 1.0f : SCALE_F;
#pragma unroll
        for (int v = 0; v < 4; ++v) {
            __nv_bfloat162 h01, l01, h23, l23;
            split2(acc[0][v] * s, acc[1][v] * s, h01, l01);
            split2(acc[2][v] * s, acc[3][v] * s, h23, l23);
            size_t base = ((size_t)h * L + n0 + v) * E + e0;
            *(__nv_bfloat162*)&Dh[base] = h01;
            *(__nv_bfloat162*)&Dh[base + 2] = h23;
            *(__nv_bfloat162*)&Dl[base] = l01;
            *(__nv_bfloat162*)&Dl[base + 2] = l23;
        }
    } else {                               // V -> [h][e][l]
#pragma unroll
        for (int u = 0; u < 4; ++u) {
            __nv_bfloat162 h01, l01, h23, l23;
            split2(acc[u][0], acc[u][1], h01, l01);
            split2(acc[u][2], acc[u][3], h23, l23);
            size_t base = ((size_t)h * E + e0 + u) * L + n0;
            *(__nv_bfloat162*)&g_Vh[base] = h01;
            *(__nv_bfloat162*)&g_Vh[base + 2] = h23;
            *(__nv_bfloat162*)&g_Vl[base] = l01;
            *(__nv_bfloat162*)&g_Vl[base + 2] = l23;
        }
    }
}

// ---------------------------------------------------------------------------
// mma.sync flash attention on pre-packed bf16 operands.
// ---------------------------------------------------------------------------
#define SQK 136
#define SVP 72
#define S_QH 0
#define S_QL 17408
#define S_KH 34816
#define S_KL 52224
#define S_VH 69632
#define S_VL 88064
#define S_PH 106496
#define S_PL 115712
#define S_LS 124928
#define S_RED 125184
#define ATTN_SMEM 126208

__global__ __launch_bounds__(256, 1) void attn_kernel() {
    extern __shared__ __align__(128) char smc[];
    const uint32_t sb = smem_u32(smc);
    const int t = threadIdx.x, w = t >> 5, ln = t & 31;
    const int h = blockIdx.y, px = blockIdx.x;
    float* l_s = (float*)(smc + S_LS);
    float* red = (float*)(smc + S_RED);

    const __nv_bfloat16* Qh = g_Qh + (size_t)h * L * E;
    const __nv_bfloat16* Ql = g_Ql + (size_t)h * L * E;
    const __nv_bfloat16* Kh = g_Kh + (size_t)h * L * E;
    const __nv_bfloat16* Kl = g_Kl + (size_t)h * L * E;
    const __nv_bfloat16* Vh = g_Vh + (size_t)h * E * L;
    const __nv_bfloat16* Vl = g_Vl + (size_t)h * E * L;

    const int wi = w & 3, wj = w >> 2;
    const int iw = wi * 16, jw = wj * 32;
    const int mA = ln >> 3, g8 = ln & 7;
    const int sArow = iw + g8 + (mA & 1) * 8;
    const int sAcol = (mA >> 1) * 8;
    const int sBrow = g8 + (mA >> 1) * 8;
    const int sBcol = (mA & 1) * 8;
    const int ew = w * 16;
    const int pArow = ew + g8 + (mA & 1) * 8;
    const int pAcol = (mA >> 1) * 8;
    const int pBrow = g8 + (mA & 1) * 8;
    const int pBcol = (mA >> 1) * 8;

#pragma unroll 1
    for (int ts = 0; ts < 2; ++ts) {
        const int jt = ts ? px : (31 - px);
        const int qb = jt << 6;
        __syncthreads();   // prior epilogue reads done

        // Q tile copy (bf16, 64 rows x 16 uint4, hi+lo)
#pragma unroll
        for (int r = 0; r < 4; ++r) {
            int id = t + r * 256, row = id >> 4, c16 = id & 15;
            const uint4* sh = (const uint4*)(Qh + (size_t)(qb + row) * E) + c16;
            const uint4* sl = (const uint4*)(Ql + (size_t)(qb + row) * E) + c16;
            *(uint4*)(smc + S_QH + row * 272 + c16 * 16) = *sh;
            *(uint4*)(smc + S_QL + row * 272 + c16 * 16) = *sl;
        }
        if (t < 64) l_s[t] = 0.f;

        float bacc[8][4];
#pragma unroll
        for (int u = 0; u < 8; u++)
#pragma unroll
            for (int v = 0; v < 4; v++) bacc[u][v] = 0.f;

#pragma unroll 1
        for (int ib = 0; ib <= jt; ++ib) {
            __syncthreads();   // prev PV reads done; Q visible on first iter
            // K tile copy [i][e]
#pragma unroll
            for (int r = 0; r < 4; ++r) {
                int id = t + r * 256, row = id >> 4, c16 = id & 15;
                const uint4* sh = (const uint4*)(Kh + (size_t)(ib * 64 + row) * E) + c16;
                const uint4* sl = (const uint4*)(Kl + (size_t)(ib * 64 + row) * E) + c16;
                *(uint4*)(smc + S_KH + row * 272 + c16 * 16) = *sh;
                *(uint4*)(smc + S_KL + row * 272 + c16 * 16) = *sl;
            }
            // V tile copy [e][i]: 128 rows x 8 uint4
#pragma unroll
            for (int r = 0; r < 4; ++r) {
                int id = t + r * 256, row = id >> 3, c8 = id & 7;
                const uint4* sh = (const uint4*)(Vh + (size_t)row * L + ib * 64) + c8;
                const uint4* sl = (const uint4*)(Vl + (size_t)row * L + ib * 64) + c8;
                *(uint4*)(smc + S_VH + row * 144 + c8 * 16) = *sh;
                *(uint4*)(smc + S_VL + row * 144 + c8 * 16) = *sl;
            }
            __syncthreads();   // K/V ready

            // ---- S = K^T Q, 3-term compensated ----
            float sacc[4][4];
#pragma unroll
            for (int u = 0; u < 4; u++)
#pragma unroll
                for (int v = 0; v < 4; v++) sacc[u][v] = 0.f;
#pragma unroll
            for (int ks = 0; ks < 8; ++ks) {
                int e0 = ks * 16;
                uint32_t ah[4], al[4];
                ldsm4(ah, sb + S_KH + (uint32_t)((sArow * SQK + e0 + sAcol) * 2));
                ldsm4(al, sb + S_KL + (uint32_t)((sArow * SQK + e0 + sAcol) * 2));
#pragma unroll
                for (int np = 0; np < 2; ++np) {
                    int j16 = jw + np * 16;
                    uint32_t bh[4], bl[4];
                    uint32_t boff = (uint32_t)(((j16 + sBrow) * SQK + e0 + sBcol) * 2);
                    ldsm4(bh, sb + S_QH + boff);
                    ldsm4(bl, sb + S_QL + boff);
                    mma_bf16(sacc[np * 2], ah, bh);
                    mma_bf16(sacc[np * 2], ah, bl);
                    mma_bf16(sacc[np * 2], al, bh);
                    mma_bf16(sacc[np * 2 + 1], ah, bh + 2);
                    mma_bf16(sacc[np * 2 + 1], ah, bl + 2);
                    mma_bf16(sacc[np * 2 + 1], al, bh + 2);
                }
            }

            // ---- exp + causal mask + P hi/lo + column sums ----
            const int rl0 = iw + (ln >> 2);
            const int i0g = ib * 64 + rl0;
#pragma unroll
            for (int nt = 0; nt < 4; ++nt) {
                int jc = jw + nt * 8 + (ln & 3) * 2;
                int jg = qb + jc;
                float p0 = (i0g <= jg)     ? __expf(sacc[nt][0]) : 0.f;
                float p1 = (i0g <= jg + 1) ? __expf(sacc[nt][1]) : 0.f;
                float p2 = (i0g + 8 <= jg)     ? __expf(sacc[nt][2]) : 0.f;
                float p3 = (i0g + 8 <= jg + 1) ? __expf(sacc[nt][3]) : 0.f;
                __nv_bfloat162 h01, l01, h23, l23;
                split2(p0, p1, h01, l01);
                split2(p2, p3, h23, l23);
                int o0 = (rl0 * SVP + jc) * 2;
                int o1 = ((rl0 + 8) * SVP + jc) * 2;
                *(__nv_bfloat162*)(smc + S_PH + o0) = h01;
                *(__nv_bfloat162*)(smc + S_PH + o1) = h23;
                *(__nv_bfloat162*)(smc + S_PL + o0) = l01;
                *(__nv_bfloat162*)(smc + S_PL + o1) = l23;
                float cs0 = p0 + p2, cs1 = p1 + p3;
#pragma unroll
                for (int off = 4; off < 32; off <<= 1) {
                    cs0 += __shfl_xor_sync(0xffffffffu, cs0, off);
                    cs1 += __shfl_xor_sync(0xffffffffu, cs1, off);
                }
                if (ln < 4) { red[wi * 64 + jc] = cs0; red[wi * 64 + jc + 1] = cs1; }
            }
            __syncthreads();   // P + red ready
            if (t < 64) l_s[t] += red[t] + red[64 + t] + red[128 + t] + red[192 + t];

            // ---- PV, 3-term ----
#pragma unroll
            for (int ks = 0; ks < 4; ++ks) {
                int i0 = ks * 16;
                uint32_t ah[4], al[4];
                uint32_t aoff = (uint32_t)((pArow * SVP + i0 + pAcol) * 2);
                ldsm4(ah, sb + S_VH + aoff);
                ldsm4(al, sb + S_VL + aoff);
#pragma unroll
                for (int np = 0; np < 4; ++np) {
                    int j16 = np * 16;
                    uint32_t bh[4], bl[4];
                    uint32_t boff = (uint32_t)(((i0 + pBrow) * SVP + j16 + pBcol) * 2);
                    ldsm4t(bh, sb + S_PH + boff);
                    ldsm4t(bl, sb + S_PL + boff);
                    mma_bf16(bacc[np * 2], ah, bh);
                    mma_bf16(bacc[np * 2], ah, bl);
                    mma_bf16(bacc[np * 2], al, bh);
                    mma_bf16(bacc[np * 2 + 1], ah, bh + 2);
                    mma_bf16(bacc[np * 2 + 1], ah, bl + 2);
                    mma_bf16(bacc[np * 2 + 1], al, bh + 2);
                }
            }
        }
        __syncthreads();   // l_s final

        // epilogue: normalize + split + store b hi/lo at [l][he]
        const int r0 = ew + (ln >> 2);
#pragma unroll
        for (int nt = 0; nt < 8; ++nt) {
            int jc = nt * 8 + (ln & 3) * 2;
            float li0 = 1.0f / l_s[jc], li1 = 1.0f / l_s[jc + 1];
            float vv[4] = {bacc[nt][0] * li0, bacc[nt][1] * li1,
                           bacc[nt][2] * li0, bacc[nt][3] * li1};
            int ee[4] = {r0, r0, r0 + 8, r0 + 8};
            int jj[4] = {jc, jc + 1, jc, jc + 1};
#pragma unroll
            for (int q = 0; q < 4; ++q) {
                __nv_bfloat16 hv = __float2bfloat16(vv[q]);
                __nv_bfloat16 lv = __float2bfloat16(vv[q] - __bfloat162float(hv));
                size_t base = (size_t)(qb + jj[q]) * HE + h * E + ee[q];
                g_bh[base] = hv;
                g_bl[base] = lv;
            }
        }
    }
}

// ---------------------------------------------------------------------------
// gemm_out via mma.sync: out = Ah/Al(128x1024) @ bh/bl(1024x2048), 3-term.
// Grid 64: n tile = 32 l columns. A [m][k], B [n][k] both k-contiguous.
// ---------------------------------------------------------------------------
#define O_AH 0
#define O_AL 18432
#define O_BH 36864
#define O_BL 41472

__global__ __launch_bounds__(256) void gemm_out_tc(float* __restrict__ out) {
    __shared__ __align__(16) char sm2[46080];
    const uint32_t sb = smem_u32(sm2);
    const int t = threadIdx.x, w = t >> 5, ln = t & 31;
    const int bn = blockIdx.x * 32;
    const int mbase = w * 16;
    const int mA = ln >> 3, g8 = ln & 7;
    const int aRow = mbase + g8 + (mA & 1) * 8;
    const int aCol = (mA >> 1) * 8;
    const int bRow = g8 + (mA >> 1) * 8;
    const int bCol = (mA & 1) * 8;

    float acc[4][4];
#pragma unroll
    for (int u = 0; u < 4; u++)
#pragma unroll
        for (int v = 0; v < 4; v++) acc[u][v] = 0.f;

    for (int kc = 0; kc < 16; ++kc) {
        const int k0 = kc * 64;
        __syncthreads();
        // A chunk: 128 rows x 8 uint4 (hi+lo)
#pragma unroll
        for (int r = 0; r < 4; ++r) {
            int id = t + r * 256, row = id >> 3, c8 = id & 7;
            *(uint4*)(sm2 + O_AH + row * 144 + c8 * 16) =
                *((const uint4*)(g_Ah + (size_t)row * HE + k0) + c8);
            *(uint4*)(sm2 + O_AL + row * 144 + c8 * 16) =
                *((const uint4*)(g_Al + (size_t)row * HE + k0) + c8);
        }
        // B chunk: 32 rows x 8 uint4
        {
            int row = t >> 3, c8 = t & 7;
            *(uint4*)(sm2 + O_BH + row * 144 + c8 * 16) =
                *((const uint4*)(g_bh + (size_t)(bn + row) * HE + k0) + c8);
            *(uint4*)(sm2 + O_BL + row * 144 + c8 * 16) =
                *((const uint4*)(g_bl + (size_t)(bn + row) * HE + k0) + c8);
        }
        __syncthreads();
#pragma unroll
        for (int kf = 0; kf < 4; ++kf) {
            int ko = kf * 16;
            uint32_t ah[4], al[4];
            uint32_t aoff = (uint32_t)((aRow * 72 + ko + aCol) * 2);
            ldsm4(ah, sb + O_AH + aoff);
            ldsm4(al, sb + O_AL + aoff);
#pragma unroll
            for (int np = 0; np < 2; ++np) {
                int n16 = np * 16;
                uint32_t bh[4], bl[4];
                uint32_t boff = (uint32_t)(((n16 + bRow) * 72 + ko + bCol) * 2);
                ldsm4(bh, sb + O_BH + boff);
                ldsm4(bl, sb + O_BL + boff);
                mma_bf16(acc[np * 2], ah, bh);
                mma_bf16(acc[np * 2], ah, bl);
                mma_bf16(acc[np * 2], al, bh);
                mma_bf16(acc[np * 2 + 1], ah, bh + 2);
                mma_bf16(acc[np * 2 + 1], ah, bl + 2);
                mma_bf16(acc[np * 2 + 1], al, bh + 2);
            }
        }
    }
    // epilogue scatter
    const int r0 = mbase + (ln >> 2);
#pragma unroll
    for (int nf = 0; nf < 4; ++nf) {
        int j0 = bn + nf * 8 + (ln & 3) * 2;
        int ee[4] = {r0, r0, r0 + 8, r0 + 8};
        int jj[4] = {j0, j0 + 1, j0, j0 + 1};
#pragma unroll
        for (int q = 0; q < 4; ++q) {
            int dst = (jj[q] < L - 1) ? (E + jj[q] * E + ee[q]) : (2 * E * L + ee[q]);
            out[dst] = acc[nf][q];
        }
    }
}

// ---------------------------------------------------------------------------
extern "C" void kernel_launch(void* const* d_in, const int* in_sizes, int n_in,
                              void* d_out, int out_size) {
    const int* sq = (const int*)d_in[0];
    const int* cq = (const int*)d_in[1];
    const float* ir = (const float*)d_in[2];
    const float* uir = (const float*)d_in[3];
    const float* wr = (const float*)d_in[4];
    const float* Wq = (const float*)d_in[5];
    const float* Wk = (const float*)d_in[6];
    const float* Wv = (const float*)d_in[7];
    const float* Hagg = (const float*)d_in[8];
    float* out = (float*)d_out;
    cudaFuncSetAttribute(attn_kernel, cudaFuncAttributeMaxDynamicSharedMemorySize, ATTN_SMEM);
    build_I_kernel<<<(E * L) / 256, 256>>>(sq, cq, ir, wr, uir, out);
    prep_A_kernel<<<256, 256>>>(Hagg);
    gemm_qkv_kernel<<<dim3(32, 16, 3), 256>>>(Wq, Wk, Wv);
    attn_kernel<<<dim3(16, H), 256, ATTN_SMEM>>>();
    gemm_out_tc<<<64, 256>>>(out);
}